// round 13
// baseline (speedup 1.0000x reference)
#include <cuda_runtime.h>

// DenseWarpLayer: bilinear warp, N=8, H=512, W=512, C=32 fp32.
// R13 = R10/R12 (best: 92.2us) with the one untouched axis changed:
// block granularity. 128 threads x 16 blocks/SM instead of 256 x 8 —
// identical 64 warps/SM, identical warp-level memory pattern (task->pixel
// decode depends only on the global thread index), but finer CTA-scheduler
// slots to close the achieved-occupancy gap (89-94% observed vs 100%
// theoretical). Everything else byte-identical to the proven best:
// persistent single-wave grid, 8 threads/pixel full-128B-line warp
// accesses, 2 sequential pixels/task with hoisted flow loads, 32 regs,
// 1-ahead L1 flow prefetch.
//
// Ledger: register ILP (R2/R3/R7) worse; cp.async (R8) worse; L2->L1
// conversion (R6) flat; occupancy wave-sizing (R9) ~flat; flow prefetch
// (R10) +1%; L2 prefetch (R11) 37% worse. Kernel is at compulsory traffic
// (~510MB) x mixed-R/W HBM ceiling (~69% of 8TB/s).

#define N_ 8
#define H_ 512
#define W_ 512
#define C4_ 8u            // 32 channels = 8 float4
#define ROW4 (W_ * C4_)   // float4 per image row = 4096
#define TPB 128u
#define NBLOCKS 2368u     // 148 SMs * 16 blocks -> exactly one wave
#define NTHREADS (NBLOCKS * TPB)
#define NTASKS 8388608u   // N*H*W*8 / 2 pixel-pair tasks
#define PIX_STRIDE 75776u // pixel offset between successive iterations
#define MAX_PIX 2097151u  // N*H*W - 1

__device__ __forceinline__ unsigned gather_base(unsigned pix, unsigned c4,
                                                const float2 fl,
                                                float& ax, float& ay)
{
    const unsigned w = pix & (W_ - 1);
    const unsigned h = (pix >> 9) & (H_ - 1);
    const unsigned n = pix >> 18;

    const float qy = (float)h - fl.x;
    const float qx = (float)w - fl.y;

    float fyf = floorf(qy);
    float fxf = floorf(qx);
    fyf = fminf(fmaxf(fyf, 0.0f), (float)(H_ - 2));
    fxf = fminf(fmaxf(fxf, 0.0f), (float)(W_ - 2));

    ay = fminf(fmaxf(qy - fyf, 0.0f), 1.0f);
    ax = fminf(fmaxf(qx - fxf, 0.0f), 1.0f);

    return ((n * H_ + (unsigned)(int)fyf) * W_ + (unsigned)(int)fxf) * C4_ + c4;
}

__device__ __forceinline__ float4 bilerp4(const float4 tl, const float4 tr,
                                          const float4 bl, const float4 br,
                                          const float ax, const float ay)
{
    float4 r; float top, bot;
    top = tl.x + ax * (tr.x - tl.x); bot = bl.x + ax * (br.x - bl.x);
    r.x = top + ay * (bot - top);
    top = tl.y + ax * (tr.y - tl.y); bot = bl.y + ax * (br.y - bl.y);
    r.y = top + ay * (bot - top);
    top = tl.z + ax * (tr.z - tl.z); bot = bl.z + ax * (br.z - bl.z);
    r.z = top + ay * (bot - top);
    top = tl.w + ax * (tr.w - tl.w); bot = bl.w + ax * (br.w - bl.w);
    r.w = top + ay * (bot - top);
    return r;
}

__device__ __forceinline__ void do_pixel(const float4* __restrict__ img4,
                                         float4* __restrict__ out4,
                                         unsigned pix, unsigned c4,
                                         const float2 fl)
{
    float ax, ay;
    const unsigned rb = gather_base(pix, c4, fl, ax, ay);

    const float4 tl = __ldg(img4 + rb);
    const float4 tr = __ldg(img4 + rb + C4_);
    const float4 bl = __ldg(img4 + rb + ROW4);
    const float4 br = __ldg(img4 + rb + ROW4 + C4_);

    out4[pix * C4_ + c4] = bilerp4(tl, tr, bl, br, ax, ay);
}

__global__ __launch_bounds__(TPB, 16)
void dense_warp_kernel(const float* __restrict__ image,
                       const float* __restrict__ flow,
                       float* __restrict__ out)
{
    const float2* fl2  = reinterpret_cast<const float2*>(flow);
    const float4* img4 = reinterpret_cast<const float4*>(image);
    float4*       out4 = reinterpret_cast<float4*>(out);

    const unsigned tid0 = blockIdx.x * TPB + threadIdx.x;

    #pragma unroll 1
    for (unsigned task = tid0; task < NTASKS; task += NTHREADS) {
        const unsigned c4   = task & 7u;
        const unsigned slot = task >> 3;
        const unsigned grp  = slot >> 2;
        const unsigned r    = slot & 3u;
        const unsigned pix0 = grp * 8u + r;
        const unsigned pix1 = pix0 + 4u;

        // prefetch NEXT iteration's flow line (both pixels' float2 values
        // live in the same 128B line); clamped to stay in-buffer.
        {
            const unsigned npix = min(pix0 + PIX_STRIDE, MAX_PIX);
            asm volatile("prefetch.global.L1 [%0];" :: "l"(fl2 + npix));
        }

        const float2 fl0 = __ldg(fl2 + pix0);
        const float2 fl1 = __ldg(fl2 + pix1);

        do_pixel(img4, out4, pix0, c4, fl0);
        do_pixel(img4, out4, pix1, c4, fl1);
    }
}

extern "C" void kernel_launch(void* const* d_in, const int* in_sizes, int n_in,
                              void* d_out, int out_size)
{
    const float* image = (const float*)d_in[0];
    const float* flow  = (const float*)d_in[1];
    float* out = (float*)d_out;

    dense_warp_kernel<<<NBLOCKS, TPB>>>(image, flow, out);
}